// round 17
// baseline (speedup 1.0000x reference)
#include <cuda_runtime.h>
#include <cuda_bf16.h>
#include <cuda_fp16.h>
#include <stdint.h>

#define NB  2
#define NS  2048
#define ND  1024
#define NH  16
#define NDH 64

// Scratch (allocation-free rule: __device__ globals).
__device__ __half g_W16 [4u << 20];                    // 4 x W^T single fp16: [n][k]
__device__ __half g_X16 [3u << 22];                    // single-fp16 Xq/Xk/Xv [4096][1024]
__device__ __half g_AO16[1u << 22];                    // single-fp16 attn out [4096][1024]
// head-major [B,H,S,DH]: Q/K/V all single fp16 (Q pre-scaled by 0.125*log2e)
__device__ __half g_Q16[NB*NH*NS*NDH];
__device__ __half g_K16[NB*NH*NS*NDH];
__device__ __half g_V16[NB*NH*NS*NDH];

// ---------------------------------------------------------------------------
// helpers
// ---------------------------------------------------------------------------
__device__ __forceinline__ uint32_t smem_u32(const void* p) {
    uint32_t a;
    asm("{ .reg .u64 t; cvta.to.shared.u64 t, %1; cvt.u32.u64 %0, t; }" : "=r"(a) : "l"(p));
    return a;
}
__device__ __forceinline__ void cpasync16(uint32_t dst, const void* src) {
    asm volatile("cp.async.cg.shared.global [%0], [%1], 16;" :: "r"(dst), "l"(src));
}
#define CP_COMMIT() asm volatile("cp.async.commit_group;" ::: "memory")
#define CP_WAIT0()  asm volatile("cp.async.wait_group 0;" ::: "memory")
#define CP_WAIT1()  asm volatile("cp.async.wait_group 1;" ::: "memory")
#define CP_WAIT2()  asm volatile("cp.async.wait_group 2;" ::: "memory")

#define LDSM_X4(r0, r1, r2, r3, addr)                                          \
    asm volatile("ldmatrix.sync.aligned.m8n8.x4.shared.b16 {%0,%1,%2,%3}, [%4];" \
        : "=r"(r0), "=r"(r1), "=r"(r2), "=r"(r3) : "r"(addr))
#define LDSM_X4_T(r0, r1, r2, r3, addr)                                        \
    asm volatile("ldmatrix.sync.aligned.m8n8.x4.trans.shared.b16 {%0,%1,%2,%3}, [%4];" \
        : "=r"(r0), "=r"(r1), "=r"(r2), "=r"(r3) : "r"(addr))

#define MMA_F16(d, a, b)                                                       \
    asm volatile("mma.sync.aligned.m16n8k16.row.col.f32.f16.f16.f32 "          \
        "{%0,%1,%2,%3},{%4,%5,%6,%7},{%8,%9},{%0,%1,%2,%3};"                   \
        : "+f"((d)[0]), "+f"((d)[1]), "+f"((d)[2]), "+f"((d)[3])               \
        : "r"((a)[0]), "r"((a)[1]), "r"((a)[2]), "r"((a)[3]),                  \
          "r"((b)[0]), "r"((b)[1]))

__device__ __forceinline__ float ex2f(float x) {
    float y; asm("ex2.approx.f32 %0, %1;" : "=f"(y) : "f"(x)); return y;
}
__device__ __forceinline__ uint32_t ex2h2(uint32_t x) {
    uint32_t y; asm("ex2.approx.f16x2 %0, %1;" : "=r"(y) : "r"(x)); return y;
}
__device__ __forceinline__ uint32_t h2pack(float a, float b) {
    __half2 h = __floats2half2_rn(a, b);
    return *(uint32_t*)&h;
}

// ---------------------------------------------------------------------------
// Prep: z 0..2 -> X fp32->fp16 convert (grid.x = 4096);
//       z 3..6 -> W transpose + fp16 convert (only grid.x < 1024 valid).
// ---------------------------------------------------------------------------
__global__ __launch_bounds__(256) void prep_kernel(
    const float* __restrict__ X0, const float* __restrict__ X1,
    const float* __restrict__ X2,
    const float* __restrict__ W0, const float* __restrict__ W1,
    const float* __restrict__ W2, const float* __restrict__ W3)
{
    const int z = blockIdx.z;
    if (z < 3) {
        const float* X = (z == 0) ? X0 : (z == 1) ? X1 : X2;
        __half* O = g_X16 + ((size_t)z << 22);
        size_t idx = (size_t)blockIdx.x * 256 + threadIdx.x;
        float4 v = *((const float4*)X + idx);
        uint2 o;
        o.x = h2pack(v.x, v.y);
        o.y = h2pack(v.z, v.w);
        *((uint2*)O + idx) = o;
    } else {
        if (blockIdx.x >= 1024) return;   // only 32x32 = 1024 W tiles
        __shared__ float t[32][33];
        int wz = z - 3;
        const float* W = (wz == 0) ? W0 : (wz == 1) ? W1 : (wz == 2) ? W2 : W3;
        __half* O = g_W16 + ((size_t)wz << 20);
        int tx = threadIdx.x & 31, ty = threadIdx.x >> 5;
        int n0 = (blockIdx.x & 31) * 32, k0 = (blockIdx.x >> 5) * 32;
        #pragma unroll
        for (int i = 0; i < 4; i++)
            t[ty + i*8][tx] = W[(size_t)(k0 + ty + i*8) * ND + n0 + tx];
        __syncthreads();
        #pragma unroll
        for (int i = 0; i < 4; i++) {
            float v = t[tx][ty + i*8];
            O[(size_t)(n0 + ty + i*8) * ND + k0 + tx] = __float2half_rn(v);
        }
    }
}

// ---------------------------------------------------------------------------
// HMMA single-pass fp16 GEMM: D = A * W. Both single fp16.
// CTA 128M x 128N, BK=64, 128 threads = 4 warps, warp tile 64m x 64n,
// TRIPLE-buffered (3 x 32KB = 96KB), 2 CTAs/SM.
// ---------------------------------------------------------------------------
#define GBUF   32768
#define G_A    0
#define G_W    16384
#define GEMM_SMEM (3 * GBUF)   // 96 KB

__global__ __launch_bounds__(128, 2) void gemm_mma_kernel(float* __restrict__ Cout, int mode)
{
    extern __shared__ char smc[];
    const uint32_t sb = smem_u32(smc);
    const int tid  = threadIdx.x;
    const int wid  = tid >> 5, lane = tid & 31;
    const int z    = blockIdx.z;

    const __half *A_g, *Wg;
    float osc = 1.f;
    if (mode == 0) {
        A_g = g_X16 + ((size_t)z << 22);
        Wg  = g_W16 + ((size_t)z << 20);
        if (z == 0) osc = 0.125f * 1.44269504f;
    } else {
        A_g = g_AO16;
        Wg  = g_W16 + ((size_t)3 << 20);
    }
    const int bM = blockIdx.y * 128, bN = blockIdx.x * 128;
    const int warp_m = (wid & 1) * 64, warp_n = (wid >> 1) * 64;

    float acc[32][4];
    #pragma unroll
    for (int i = 0; i < 32; i++)
        #pragma unroll
        for (int j = 0; j < 4; j++) acc[i][j] = 0.f;

    auto cpStage = [&](int s, int buf) {
        uint32_t base = sb + buf * GBUF;
        #pragma unroll
        for (int l = 0; l < 16; l++) {
            int f = tid + l * 128;
            const __half* src;
            uint32_t dst;
            if (f < 1024) {
                int r = f >> 3, c = f & 7;
                src = A_g + (size_t)(bM + r) * ND + s * 64 + c * 8;
                dst = base + G_A + r * 128 + ((c * 16) ^ ((r & 7) * 16));
            } else {
                int g = f - 1024;
                int r = g >> 3, c = g & 7;
                src = Wg + (size_t)(bN + r) * ND + s * 64 + c * 8;
                dst = base + G_W + r * 128 + ((c * 16) ^ ((r & 7) * 16));
            }
            cpasync16(dst, src);
        }
        CP_COMMIT();
    };

    cpStage(0, 0);
    cpStage(1, 1);

    for (int s = 0; s < 16; s++) {
        const int buf = s % 3;
        if (s + 2 < 16) { cpStage(s + 2, (s + 2) % 3); CP_WAIT2(); }
        else if (s + 1 < 16) { CP_WAIT1(); }
        else { CP_WAIT0(); }
        __syncthreads();

        const uint32_t aS = sb + buf * GBUF + G_A;
        const uint32_t wS = sb + buf * GBUF + G_W;

        #pragma unroll
        for (int kk = 0; kk < 4; kk++) {
            const int k0 = kk * 16;
            uint32_t af[4][4];
            #pragma unroll
            for (int mt = 0; mt < 4; mt++) {
                int row = warp_m + mt * 16 + (lane & 15);
                uint32_t off = row * 128 + ((k0 * 2 + (lane >> 4) * 16) ^ ((row & 7) * 16));
                LDSM_X4(af[mt][0], af[mt][1], af[mt][2], af[mt][3], aS + off);
            }
            uint32_t wf[8][2];
            #pragma unroll
            for (int p = 0; p < 4; p++) {
                int n = warp_n + p * 16 + (lane & 7) + ((lane >> 4) << 3);
                uint32_t off = n * 128 + ((k0 * 2 + ((lane >> 3) & 1) * 16) ^ ((n & 7) * 16));
                LDSM_X4(wf[p*2][0], wf[p*2][1], wf[p*2+1][0], wf[p*2+1][1], wS + off);
            }
            #pragma unroll
            for (int mt = 0; mt < 4; mt++)
                #pragma unroll
                for (int nt = 0; nt < 8; nt++)
                    MMA_F16(acc[mt*8 + nt], af[mt], wf[nt]);
        }
        __syncthreads();   // all reads of buf done before it is re-filled
    }

    #pragma unroll
    for (int mt = 0; mt < 4; mt++)
        #pragma unroll
        for (int nt = 0; nt < 8; nt++) {
            int m0 = bM + warp_m + mt * 16 + (lane >> 2);
            int n  = bN + warp_n + nt * 8 + (lane & 3) * 2;
            float* a4 = acc[mt*8+nt];
            if (mode == 0) {
                int h = n >> 6, dh = n & 63;
                int b0 = m0 >> 11, s0 = m0 & 2047;
                int m1 = m0 + 8, b1 = m1 >> 11, s1 = m1 & 2047;
                size_t i0 = ((size_t)(b0 * NH + h) * NS + s0) * NDH + dh;
                size_t i1 = ((size_t)(b1 * NH + h) * NS + s1) * NDH + dh;
                __half* O = (z == 0) ? g_Q16 : (z == 1) ? g_K16 : g_V16;
                *(uint32_t*)(O + i0) = h2pack(a4[0] * osc, a4[1] * osc);
                *(uint32_t*)(O + i1) = h2pack(a4[2] * osc, a4[3] * osc);
            } else {
                *(float2*)(Cout + (size_t)m0 * ND + n)       = make_float2(a4[0], a4[1]);
                *(float2*)(Cout + (size_t)(m0 + 8) * ND + n) = make_float2(a4[2], a4[3]);
            }
        }
}

// ---------------------------------------------------------------------------
// Flash attention on HMMA, all single-fp16.
// QK 1-pass; V t=0 fragments prefetched before softmax (latency overlap);
// softmax: fp32 max + f16x2 exp2; row-sums via ones-MMA; PV 1-pass.
// 2 CTAs/SM; batch-interleaved bh mapping for load balance.
// ---------------------------------------------------------------------------
#define ATT_BUF  16384
#define ATT_SMEM (2 * ATT_BUF)

__global__ __launch_bounds__(256, 2) void attn_mma_kernel(const int* __restrict__ valid_lens)
{
    extern __shared__ char smc[];
    const uint32_t sb = smem_u32(smc);
    const int tid = threadIdx.x, wid = tid >> 5, lane = tid & 31;
    const int qb = blockIdx.x;
    // interleave batches across the wave: even y -> batch 0, odd y -> batch 1
    const int bh = ((blockIdx.y & 1) << 4) | (blockIdx.y >> 1);
    const int bb = bh >> 4, head = bh & 15;
    const int vlen = valid_lens[bb];
    const int nkb  = (vlen + 63) >> 6;

    const size_t hbase = (size_t)bh * NS * NDH;
    const __half *Q16 = g_Q16 + hbase;
    const __half *K16 = g_K16 + hbase, *V16 = g_V16 + hbase;

    const int r = lane >> 2, c2 = (lane & 3) * 2;

    uint32_t qf[4][4];
    {
        const int q0 = qb * 128 + wid * 16;
        #pragma unroll
        for (int t = 0; t < 4; t++) {
            int k0 = t * 16;
            qf[t][0] = *(const uint32_t*)(Q16 + (size_t)(q0 + r    ) * NDH + k0 + c2);
            qf[t][1] = *(const uint32_t*)(Q16 + (size_t)(q0 + r + 8) * NDH + k0 + c2);
            qf[t][2] = *(const uint32_t*)(Q16 + (size_t)(q0 + r    ) * NDH + k0 + c2 + 8);
            qf[t][3] = *(const uint32_t*)(Q16 + (size_t)(q0 + r + 8) * NDH + k0 + c2 + 8);
        }
    }

    float m_i[2] = {-1e30f, -1e30f}, l_i[2] = {0.f, 0.f};
    float o[8][4];
    #pragma unroll
    for (int i = 0; i < 8; i++)
        #pragma unroll
        for (int j = 0; j < 4; j++) o[i][j] = 0.f;

    const uint32_t ONES[2] = {0x3C003C00u, 0x3C003C00u};   // fp16 1.0 x4

    auto cpKV = [&](int kb, int buf) {
        #pragma unroll
        for (int l = 0; l < 4; l++) {
            int f   = tid + l * 256;
            int arr = f >> 9;
            int rr  = (f >> 3) & 63;
            int cc  = f & 7;
            const void* src = (arr ? V16 : K16) + (size_t)(kb * 64 + rr) * NDH + cc * 8;
            uint32_t dst = sb + buf * ATT_BUF + arr * 8192
                         + rr * 128 + ((cc * 16) ^ ((rr & 7) * 16));
            cpasync16(dst, src);
        }
        CP_COMMIT();
    };

    cpKV(0, 0);

    for (int kb = 0; kb < nkb; kb++) {
        const int buf = kb & 1;
        CP_WAIT0();
        __syncthreads();
        if (kb + 1 < nkb) cpKV(kb + 1, buf ^ 1);

        const uint32_t kS = sb + buf * ATT_BUF;
        const uint32_t vS = kS + 8192;

        // ---- S = Q K^T (1-pass fp16) ----
        float s[8][4];
        #pragma unroll
        for (int i = 0; i < 8; i++)
            #pragma unroll
            for (int j = 0; j < 4; j++) s[i][j] = 0.f;

        #pragma unroll
        for (int t = 0; t < 4; t++) {
            uint32_t kf[8][2];
            #pragma unroll
            for (int p = 0; p < 4; p++) {
                int n = p * 16 + (lane & 7) + ((lane >> 4) << 3);
                uint32_t off = n * 128 + ((t * 32 + ((lane >> 3) & 1) * 16) ^ ((n & 7) * 16));
                LDSM_X4(kf[p*2][0], kf[p*2][1], kf[p*2+1][0], kf[p*2+1][1], kS + off);
            }
            #pragma unroll
            for (int nt = 0; nt < 8; nt++)
                MMA_F16(s[nt], qf[t], kf[nt]);
        }

        // ---- prefetch V fragments for t=0 (overlaps softmax latency chain) --
        uint32_t vf0[8][2];
        #pragma unroll
        for (int p = 0; p < 4; p++) {
            int rowb = lane & 15;
            uint32_t off = rowb * 128 + ((p * 32 + (lane >> 4) * 16) ^ ((rowb & 7) * 16));
            LDSM_X4_T(vf0[p*2][0], vf0[p*2][1], vf0[p*2+1][0], vf0[p*2+1][1], vS + off);
        }

        if (kb == nkb - 1) {
            int cb = kb * 64 + c2;
            #pragma unroll
            for (int nt = 0; nt < 8; nt++) {
                int c0g = cb + nt * 8;
                if (c0g     >= vlen) { s[nt][0] = -1e30f; s[nt][2] = -1e30f; }
                if (c0g + 1 >= vlen) { s[nt][1] = -1e30f; s[nt][3] = -1e30f; }
            }
        }

        // ---- max (fp32, quad shfl) ----
        float mx0 = -1e30f, mx1 = -1e30f;
        #pragma unroll
        for (int nt = 0; nt < 8; nt++) {
            mx0 = fmaxf(mx0, fmaxf(s[nt][0], s[nt][1]));
            mx1 = fmaxf(mx1, fmaxf(s[nt][2], s[nt][3]));
        }
        mx0 = fmaxf(mx0, __shfl_xor_sync(0xffffffffu, mx0, 1));
        mx0 = fmaxf(mx0, __shfl_xor_sync(0xffffffffu, mx0, 2));
        mx1 = fmaxf(mx1, __shfl_xor_sync(0xffffffffu, mx1, 1));
        mx1 = fmaxf(mx1, __shfl_xor_sync(0xffffffffu, mx1, 2));

        float mn0 = fmaxf(m_i[0], mx0), mn1 = fmaxf(m_i[1], mx1);
        float a0 = ex2f(m_i[0] - mn0), a1 = ex2f(m_i[1] - mn1);
        m_i[0] = mn0; m_i[1] = mn1;

        // ---- P = exp2(S - m) in f16x2, directly in MMA layout ----
        uint32_t ps[4][4];
        #pragma unroll
        for (int t = 0; t < 4; t++) {
            ps[t][0] = ex2h2(h2pack(s[2*t  ][0] - mn0, s[2*t  ][1] - mn0));
            ps[t][1] = ex2h2(h2pack(s[2*t  ][2] - mn1, s[2*t  ][3] - mn1));
            ps[t][2] = ex2h2(h2pack(s[2*t+1][0] - mn0, s[2*t+1][1] - mn0));
            ps[t][3] = ex2h2(h2pack(s[2*t+1][2] - mn1, s[2*t+1][3] - mn1));
        }

        // ---- row sums via ones-MMA (fp32 accumulate, no shfl) ----
        float sacc[4] = {0.f, 0.f, 0.f, 0.f};
        #pragma unroll
        for (int t = 0; t < 4; t++)
            MMA_F16(sacc, ps[t], ONES);
        l_i[0] = l_i[0] * a0 + sacc[0];
        l_i[1] = l_i[1] * a1 + sacc[2];

        #pragma unroll
        for (int nt = 0; nt < 8; nt++) {
            o[nt][0] *= a0; o[nt][1] *= a0;
            o[nt][2] *= a1; o[nt][3] *= a1;
        }

        // ---- O += P V (1-pass; t=0 uses prefetched fragments) ----
        #pragma unroll
        for (int nt = 0; nt < 8; nt++)
            MMA_F16(o[nt], ps[0], vf0[nt]);
        #pragma unroll
        for (int t = 1; t < 4; t++) {
            uint32_t vf[8][2];
            #pragma unroll
            for (int p = 0; p < 4; p++) {
                int rowb = t * 16 + (lane & 15);
                uint32_t off = rowb * 128 + ((p * 32 + (lane >> 4) * 16) ^ ((rowb & 7) * 16));
                LDSM_X4_T(vf[p*2][0], vf[p*2][1], vf[p*2+1][0], vf[p*2+1][1], vS + off);
            }
            #pragma unroll
            for (int nt = 0; nt < 8; nt++)
                MMA_F16(o[nt], ps[t], vf[nt]);
        }
    }

    // epilogue: single fp16 to g_AO16 [B*S][D]
    const float inv0 = 1.f / l_i[0], inv1 = 1.f / l_i[1];
    const int row0 = qb * 128 + wid * 16 + r;
    const size_t base0 = (size_t)(bb * NS + row0    ) * ND + head * 64;
    const size_t base1 = (size_t)(bb * NS + row0 + 8) * ND + head * 64;
    #pragma unroll
    for (int nt = 0; nt < 8; nt++) {
        *(uint32_t*)(g_AO16 + base0 + nt * 8 + c2) = h2pack(o[nt][0] * inv0, o[nt][1] * inv0);
        *(uint32_t*)(g_AO16 + base1 + nt * 8 + c2) = h2pack(o[nt][2] * inv1, o[nt][3] * inv1);
    }
}

// ---------------------------------------------------------------------------
extern "C" void kernel_launch(void* const* d_in, const int* in_sizes, int n_in,
                              void* d_out, int out_size)
{
    const float* q  = (const float*)d_in[0];
    const float* k  = (const float*)d_in[1];
    const float* v  = (const float*)d_in[2];
    const int*   vl = (const int*)  d_in[3];
    const float* Wq = (const float*)d_in[4];
    const float* Wk = (const float*)d_in[5];
    const float* Wv = (const float*)d_in[6];
    const float* Wo = (const float*)d_in[7];
    float* out = (float*)d_out;

    cudaFuncSetAttribute(gemm_mma_kernel, cudaFuncAttributeMaxDynamicSharedMemorySize,
                         GEMM_SMEM);
    cudaFuncSetAttribute(attn_mma_kernel, cudaFuncAttributeMaxDynamicSharedMemorySize,
                         ATT_SMEM);

    prep_kernel<<<dim3(4096, 1, 7), 256>>>(q, k, v, Wq, Wk, Wv, Wo);

    gemm_mma_kernel<<<dim3(ND / 128, (NB * NS) / 128, 3), 128, GEMM_SMEM>>>(out, 0);

    attn_mma_kernel<<<dim3(NS / 128, NB * NH), 256, ATT_SMEM>>>(vl);

    gemm_mma_kernel<<<dim3(ND / 128, (NB * NS) / 128, 1), 128, GEMM_SMEM>>>(out, 1);
}